// round 6
// baseline (speedup 1.0000x reference)
#include <cuda_runtime.h>
#include <math.h>

#define BB 4
#define HH 192
#define WW 192
#define CC 64
#define HO 186
#define BHW (BB*HH*WW)          /* 147456 */
#define NELEM (BB*HH*WW*CC)     /* 9437184 */

// ---------------- scratch (device globals; no allocs allowed) ----------------
__device__ __align__(256) float g_X[3][NELEM]; // x-conv results, orders 0..2
__device__ float  g_P[2*10*BHW];   // [(sigma*10+e)][b*H*W] channel-reduced products
__device__ float2 g_fxe[2][7];     // x-factors folded: (ord0, ord2) taps 0..R (R = center)
__device__ float  g_fxo[2][6];     // x-factor order1 taps 0..R-1 (antisym; center==0)
__device__ float4 g_fe[2][7];      // y-factors even maps: (L0=m0, L3=m3, L2=m2, L5=m5)
__device__ float2 g_fo[2][6];      // y-factors odd  maps: (L1=m1, L4=m4)
__device__ float  g_wy[7];         // integrator y factor
__device__ float  g_wx[7];         // integrator x factor

// ---------------- factorization of the 2-D kernels into 1-D factors ----------
__device__ void factor_one(const float* K, int Ksz, int s) {
    const int R = (Ksz - 1) / 2;
    const int canon[3] = {0, 2, 5};          // canonical kernel per x-order (k=0,1,2)
    const int kxo[6]   = {0, 0, 1, 0, 1, 2}; // x-order of kernel m
    int   c0s[3];
    float fx[3][13];
    for (int o = 0; o < 3; ++o) {
        const float* Km = K + canon[o]*Ksz*Ksz*CC;
        int r0 = 0, c0 = 0; float best = -1.f;
        for (int i = 0; i < Ksz; ++i)
            for (int j = 0; j < Ksz; ++j) {
                float v = fabsf(Km[(i*Ksz + j)*CC]);
                if (v > best) { best = v; r0 = i; c0 = j; }
            }
        float piv = Km[(r0*Ksz + c0)*CC];
        for (int j = 0; j < Ksz; ++j) fx[o][j] = Km[(r0*Ksz + j)*CC] / piv;
        c0s[o] = c0;
    }
    for (int t = 0; t <= R; ++t) g_fxe[s][t] = make_float2(fx[0][t], fx[2][t]);
    for (int t = 0; t <  R; ++t) g_fxo[s][t] = fx[1][t];

    const float comb[6] = {1.f, 1.f, 1.f, 1.f, 1.41421356237309515f, 1.f}; // sqrt(C(j,k))
    float fy[6][13];
    for (int m = 0; m < 6; ++m) {
        int c0 = c0s[kxo[m]];
        for (int i = 0; i < Ksz; ++i)
            fy[m][i] = K[(m*Ksz*Ksz + i*Ksz + c0)*CC] * comb[m];
    }
    // evens in y: m0(L0), m3(L3), m2(L2), m5(L5); odds: m1(L1), m4(L4)
    for (int t = 0; t <= R; ++t)
        g_fe[s][t] = make_float4(fy[0][t], fy[3][t], fy[2][t], fy[5][t]);
    for (int t = 0; t <  R; ++t)
        g_fo[s][t] = make_float2(fy[1][t], fy[4][t]);
}

__global__ void factorize(const float* __restrict__ k0, const float* __restrict__ k1,
                          const float* __restrict__ dgi) {
    if (threadIdx.x != 0) return;
    factor_one(k0, 7, 0);
    factor_one(k1, 13, 1);
    // integrator: 7x7 rank-1, all channels identical (take c=0)
    int r0 = 0, c0 = 0; float best = -1.f;
    for (int i = 0; i < 7; ++i)
        for (int j = 0; j < 7; ++j) {
            float v = fabsf(dgi[(i*7 + j)*CC]);
            if (v > best) { best = v; r0 = i; c0 = j; }
        }
    float piv = dgi[(r0*7 + c0)*CC];
    for (int i = 0; i < 7; ++i) g_wy[i] = dgi[(i*7 + c0)*CC];
    for (int j = 0; j < 7; ++j) g_wx[j] = dgi[(r0*7 + j)*CC] / piv;
}

// ---------------- stage 1: horizontal (x) convolution, orders 0..2 ----------
// Thread handles a float4 channel quad; symmetry folds 2K+1 taps into R sums/diffs.
template<int R>
__global__ void __launch_bounds__(256) stage1(const float* __restrict__ in, int sigma) {
    constexpr int K  = 2*R + 1;
    constexpr int XT = 64;
    __shared__ float4 s_in[(XT + 2*R)*16];
    const int b = blockIdx.z, yrow = blockIdx.y, x0 = blockIdx.x*XT;
    const int tid = threadIdx.x;
    const float4 Z4 = make_float4(0.f,0.f,0.f,0.f);
    const float4* rowv = (const float4*)(in + ((size_t)(b*HH + yrow)*WW)*CC);
    for (int t = tid; t < (XT + 2*R)*16; t += 256) {
        int xx = (t >> 4) - R + x0;
        int c4 = t & 15;
        s_in[t] = (xx >= 0 && xx < WW) ? rowv[xx*16 + c4] : Z4;
    }
    float2 fxe[R+1]; float fxo[R];
    #pragma unroll
    for (int t = 0; t <= R; ++t) fxe[t] = g_fxe[sigma][t];
    #pragma unroll
    for (int t = 0; t <  R; ++t) fxo[t] = g_fxo[sigma][t];
    __syncthreads();

    const int c4 = tid & 15, xg = tid >> 4;
    const size_t obase = ((size_t)(b*HH + yrow)*WW)*CC;
    float4* o0 = (float4*)&g_X[0][obase];
    float4* o1 = (float4*)&g_X[1][obase];
    float4* o2 = (float4*)&g_X[2][obase];
    #pragma unroll
    for (int xq = 0; xq < 4; ++xq) {
        int xi = xg*4 + xq;
        float4 a0 = Z4, a1 = Z4, a2 = Z4;
        #pragma unroll
        for (int t = 0; t < R; ++t) {
            float4 u = s_in[(xi + t)*16 + c4];
            float4 v = s_in[(xi + K - 1 - t)*16 + c4];
            float sx = u.x + v.x, sy = u.y + v.y, sz = u.z + v.z, sw = u.w + v.w;
            float dx = u.x - v.x, dy = u.y - v.y, dz = u.z - v.z, dw = u.w - v.w;
            a0.x = fmaf(fxe[t].x, sx, a0.x); a0.y = fmaf(fxe[t].x, sy, a0.y);
            a0.z = fmaf(fxe[t].x, sz, a0.z); a0.w = fmaf(fxe[t].x, sw, a0.w);
            a2.x = fmaf(fxe[t].y, sx, a2.x); a2.y = fmaf(fxe[t].y, sy, a2.y);
            a2.z = fmaf(fxe[t].y, sz, a2.z); a2.w = fmaf(fxe[t].y, sw, a2.w);
            a1.x = fmaf(fxo[t],   dx, a1.x); a1.y = fmaf(fxo[t],   dy, a1.y);
            a1.z = fmaf(fxo[t],   dz, a1.z); a1.w = fmaf(fxo[t],   dw, a1.w);
        }
        float4 m = s_in[(xi + R)*16 + c4];
        a0.x = fmaf(fxe[R].x, m.x, a0.x); a0.y = fmaf(fxe[R].x, m.y, a0.y);
        a0.z = fmaf(fxe[R].x, m.z, a0.z); a0.w = fmaf(fxe[R].x, m.w, a0.w);
        a2.x = fmaf(fxe[R].y, m.x, a2.x); a2.y = fmaf(fxe[R].y, m.y, a2.y);
        a2.z = fmaf(fxe[R].y, m.z, a2.z); a2.w = fmaf(fxe[R].y, m.w, a2.w);
        int off = (x0 + xi)*16 + c4;
        o0[off] = a0; o1[off] = a1; o2[off] = a2;
    }
}

// ---- stage 2: vertical conv (6 L maps) + outer products + channel reduce ----
// Warp = one x column, all 64 channels (2 per lane via float2). Register ring
// over y; coefficients live in SMEM (broadcast LDS) to keep regs <= 128 so two
// 256-thread blocks fit per SM. Split-butterfly reduce; one predicated STG.
template<int R, int SEGH, int NCH>
__global__ void __launch_bounds__(256, 2) stage2(int sigma) {
    constexpr int K = 2*R + 1;
    static_assert(SEGH == NCH*K, "strip must be multiple of K");
    __shared__ float4 s_fe[R+1];
    __shared__ float2 s_fo[R];
    const int tid  = threadIdx.x;
    const int warp = tid >> 5, lane = tid & 31;
    if (tid <= R) s_fe[tid] = g_fe[sigma][tid];
    if (tid >= 32 && tid < 32 + R) s_fo[tid - 32] = g_fo[sigma][tid - 32];
    __syncthreads();

    const int b    = blockIdx.z;
    const int x    = blockIdx.x*8 + warp;
    const int ys   = blockIdx.y*SEGH;          // SEGH % K == 0 -> slots compile-time
    const int rs   = WW*32;                    // row stride in float2 units
    const size_t base = ((size_t)(b*HH*WW) + x)*32 + lane;
    const float2* X0 = (const float2*)g_X[0] + base;
    const float2* X1 = (const float2*)g_X[1] + base;
    const float2* X2 = (const float2*)g_X[2] + base;

    // --- per-lane reduction routing (computed once) ---
    const bool h4 = (lane & 16) != 0;
    const bool h3 = (lane & 8)  != 0;
    const bool h2 = (lane & 4)  != 0;
    const bool h1 = (lane & 2)  != 0;
    const bool two = (!h3) && (!h2);           // class holding 2 entries at L3
    const int  m4 = lane & 15;
    const int  f  = (m4==0) ? 0 : (m4==2) ? 1 : (m4==4) ? 2 : (m4==8) ? 3 : 4;
    const int  eidx = (h4 ? 5 : 0) + f;
    const bool writer = (m4==0 || m4==2 || m4==4 || m4==8 || m4==12);
    float* PbE = &g_P[(size_t)(sigma*10 + eidx)*BHW + (size_t)b*HH*WW + x];

    const float2 Z2 = make_float2(0.f, 0.f);
    float2 r0[K], r1[K], r2[K];
    #pragma unroll
    for (int j = 0; j < K - 1; ++j) {            // preload rows ys-R+j
        int yy = ys - R + j;
        const int sl = (j + K - R) % K;
        bool ok = (yy >= 0 && yy < HH);
        r0[sl] = ok ? X0[(size_t)yy*rs] : Z2;
        r1[sl] = ok ? X1[(size_t)yy*rs] : Z2;
        r2[sl] = ok ? X2[(size_t)yy*rs] : Z2;
    }

    int y = ys;
    for (int ch = 0; ch < NCH; ++ch) {
        #pragma unroll
        for (int i = 0; i < K; ++i, ++y) {
            {   // load row y+R into slot (i+R)%K
                const int slN = (i + R) % K;
                int yy = y + R;
                bool ok = yy < HH;
                r0[slN] = ok ? X0[(size_t)yy*rs] : Z2;
                r1[slN] = ok ? X1[(size_t)yy*rs] : Z2;
                r2[slN] = ok ? X2[(size_t)yy*rs] : Z2;
            }
            float2 L0=Z2, L1=Z2, L2=Z2, L3=Z2, L4=Z2, L5=Z2;
            #pragma unroll
            for (int j = 0; j < R; ++j) {
                const int sa = (i + j + (K - R)) % K;
                const int sb = (i + (K - 1 - j) + (K - R)) % K;
                float4 fe = s_fe[j];
                float2 fo = s_fo[j];
                float2 a0 = r0[sa], b0 = r0[sb];
                float2 a1 = r1[sa], b1 = r1[sb];
                float2 a2 = r2[sa], b2 = r2[sb];
                float s0x = a0.x + b0.x, s0y = a0.y + b0.y;
                float d0x = a0.x - b0.x, d0y = a0.y - b0.y;
                float s1x = a1.x + b1.x, s1y = a1.y + b1.y;
                float d1x = a1.x - b1.x, d1y = a1.y - b1.y;
                float s2x = a2.x + b2.x, s2y = a2.y + b2.y;
                L0.x = fmaf(fe.x, s0x, L0.x); L0.y = fmaf(fe.x, s0y, L0.y);
                L3.x = fmaf(fe.y, s0x, L3.x); L3.y = fmaf(fe.y, s0y, L3.y);
                L2.x = fmaf(fe.z, s1x, L2.x); L2.y = fmaf(fe.z, s1y, L2.y);
                L5.x = fmaf(fe.w, s2x, L5.x); L5.y = fmaf(fe.w, s2y, L5.y);
                L1.x = fmaf(fo.x, d0x, L1.x); L1.y = fmaf(fo.x, d0y, L1.y);
                L4.x = fmaf(fo.y, d1x, L4.x); L4.y = fmaf(fo.y, d1y, L4.y);
            }
            {   // center tap: slot == i  (odd maps have exact zero center)
                float4 fe = s_fe[R];
                L0.x = fmaf(fe.x, r0[i].x, L0.x); L0.y = fmaf(fe.x, r0[i].y, L0.y);
                L3.x = fmaf(fe.y, r0[i].x, L3.x); L3.y = fmaf(fe.y, r0[i].y, L3.y);
                L2.x = fmaf(fe.z, r1[i].x, L2.x); L2.y = fmaf(fe.z, r1[i].y, L2.y);
                L5.x = fmaf(fe.w, r2[i].x, L5.x); L5.y = fmaf(fe.w, r2[i].y, L5.y);
            }
            // per-lane products (2 channels folded)
            float p0 = fmaf(L0.y, L0.y, L0.x*L0.x);
            float p1 = fmaf(L1.y, L1.y, L1.x*L1.x);
            float p2 = fmaf(L1.y, L2.y, L1.x*L2.x);
            float p3 = fmaf(L2.y, L2.y, L2.x*L2.x);
            float p4 = fmaf(L3.y, L3.y, L3.x*L3.x);
            float p5 = fmaf(L3.y, L4.y, L3.x*L4.x);
            float p6 = fmaf(L3.y, L5.y, L3.x*L5.x);
            float p7 = fmaf(L4.y, L4.y, L4.x*L4.x);
            float p8 = fmaf(L4.y, L5.y, L4.x*L5.x);
            float p9 = fmaf(L5.y, L5.y, L5.x*L5.x);

            // --- split-butterfly: 10 entries, halving entry set each level ---
            float v0, v1, v2, v3, v4;
            {
                float q, t;
                q = h4 ? p0 : p5; t = __shfl_xor_sync(0xffffffffu, q, 16); v0 = (h4 ? p5 : p0) + t;
                q = h4 ? p1 : p6; t = __shfl_xor_sync(0xffffffffu, q, 16); v1 = (h4 ? p6 : p1) + t;
                q = h4 ? p2 : p7; t = __shfl_xor_sync(0xffffffffu, q, 16); v2 = (h4 ? p7 : p2) + t;
                q = h4 ? p3 : p8; t = __shfl_xor_sync(0xffffffffu, q, 16); v3 = (h4 ? p8 : p3) + t;
                q = h4 ? p4 : p9; t = __shfl_xor_sync(0xffffffffu, q, 16); v4 = (h4 ? p9 : p4) + t;
            }
            float w0, w1, w2;
            {
                float q0 = h3 ? v0 : v3;
                float q1 = h3 ? v1 : v4;
                float q2 = v2;
                float t0 = __shfl_xor_sync(0xffffffffu, q0, 8);
                float t1 = __shfl_xor_sync(0xffffffffu, q1, 8);
                float t2 = __shfl_xor_sync(0xffffffffu, q2, 8);
                if (!h3) { w0 = v0 + t0; w1 = v1 + t1; w2 = v2 + t2; }
                else     { w0 = v3 + t0; w1 = v4 + t1; w2 = 0.f; }
            }
            float u0, u1;
            {
                float q0 = h2 ? w0 : (h3 ? w1 : w2);
                float q1 = w1;
                float t0 = __shfl_xor_sync(0xffffffffu, q0, 4);
                float t1 = __shfl_xor_sync(0xffffffffu, q1, 4);
                if (!h3) {
                    if (!h2) { u0 = w0 + t0; u1 = w1 + t1; }
                    else     { u0 = w2 + t0; u1 = 0.f; }
                } else {
                    u0 = (h2 ? w1 : w0) + t0; u1 = 0.f;
                }
            }
            float z;
            {
                float q = two ? (h1 ? u0 : u1) : u0;
                float t = __shfl_xor_sync(0xffffffffu, q, 2);
                z = (two ? (h1 ? u1 : u0) : u0) + t;
            }
            z += __shfl_xor_sync(0xffffffffu, z, 1);

            if (writer && y < HH)
                PbE[y*WW] = z;
        }
    }
}

// ------- stage 3: separable 7x7 VALID integration + Newton-identity ESPs ----
// Integrator is rank-1 (wy ⊗ wx): two-pass conv in smem, 10 maps per chunk.
__global__ void __launch_bounds__(256) stage3(float* __restrict__ out) {
    __shared__ float sP[10*22*22];
    __shared__ float sQ[10*22*16];
    const int tid = threadIdx.x;
    const int b = blockIdx.z;
    const int y0 = blockIdx.y*16, x0 = blockIdx.x*16;
    const int ty = tid >> 4, tx = tid & 15;
    const int yo = y0 + ty, xo = x0 + tx;
    const bool inb = (yo < HO) && (xo < HO);

    float wy[7], wx[7];
    #pragma unroll
    for (int i = 0; i < 7; ++i) { wy[i] = g_wy[i]; wx[i] = g_wx[i]; }

    float M[20];
    #pragma unroll
    for (int chunk = 0; chunk < 2; ++chunk) {
        // load 10 maps' 22x22 tiles
        for (int idx = tid; idx < 10*484; idx += 256) {
            int se  = idx / 484;
            int rem = idx - se*484;
            int r   = rem / 22;
            int cc2 = rem - r*22;
            int y = y0 + r, x = x0 + cc2;
            float v = 0.f;
            if (y < HH && x < WW)
                v = g_P[(size_t)(chunk*10 + se)*BHW + (size_t)(b*HH + y)*WW + x];
            sP[idx] = v;
        }
        __syncthreads();
        // pass 1: horizontal (x) conv 22x22 -> 22x16
        for (int idx = tid; idx < 10*352; idx += 256) {
            int se  = idx / 352;
            int rem = idx - se*352;
            int r   = rem >> 4;
            int cx  = rem & 15;
            const float* row = &sP[se*484 + r*22 + cx];
            float a = 0.f;
            #pragma unroll
            for (int j = 0; j < 7; ++j) a = fmaf(wx[j], row[j], a);
            sQ[idx] = a;
        }
        __syncthreads();
        // pass 2: vertical (y) conv 22x16 -> 16x16 (each thread its own output)
        #pragma unroll
        for (int s = 0; s < 10; ++s) {
            float a = 0.f;
            const float* col = &sQ[s*352 + ty*16 + tx];
            #pragma unroll
            for (int i = 0; i < 7; ++i) a = fmaf(wy[i], col[i*16], a);
            M[chunk*10 + s] = a;
        }
        __syncthreads();
    }
    if (!inb) return;

    const float EPSF = 2.2204460492503131e-16f;
    float res[12];
    #pragma unroll
    for (int s = 0; s < 2; ++s) {
        const float* Ms = M + s*10;
        res[s*6 + 0] = fabsf(Ms[0]) + EPSF;
        {
            float a = Ms[1], bq = Ms[2], c2v = Ms[3];
            float p1 = a + c2v;
            float p2 = a*a + 2.f*bq*bq + c2v*c2v;
            float e1 = p1;
            float e2 = 0.5f*(p1*e1 - p2);
            res[s*6 + 1] = 10.f*(fabsf(e1) + EPSF);
            res[s*6 + 2] = 10.f*sqrtf(fabsf(e2) + EPSF);
        }
        {
            float a = Ms[4], bq = Ms[5], cq = Ms[6], d = Ms[7], e = Ms[8], f = Ms[9];
            float p1 = a + d + f;
            float p2 = a*a + d*d + f*f + 2.f*(bq*bq + cq*cq + e*e);
            float p3 = a*a*a + d*d*d + f*f*f
                     + 3.f*(a*(bq*bq + cq*cq) + d*(bq*bq + e*e) + f*(cq*cq + e*e))
                     + 6.f*bq*cq*e;
            float e1 = p1;
            float e2 = 0.5f*(p1*e1 - p2);
            float e3 = (p1*e2 - p2*e1 + p3)*(1.f/3.f);
            res[s*6 + 3] = 100.f*(fabsf(e1) + EPSF);
            res[s*6 + 4] = 100.f*sqrtf(fabsf(e2) + EPSF);
            res[s*6 + 5] = 100.f*cbrtf(fabsf(e3) + EPSF);
        }
    }
    float* op = out + ((size_t)(b*HO + yo)*HO + xo)*12;
    #pragma unroll
    for (int chn = 0; chn < 12; ++chn) op[chn] = res[chn];
}

// ---------------- launcher ---------------------------------------------------
extern "C" void kernel_launch(void* const* d_in, const int* in_sizes, int n_in,
                              void* d_out, int out_size) {
    const float* in  = (const float*)d_in[0];
    const float* k0  = (const float*)d_in[1];
    const float* k1  = (const float*)d_in[2];
    const float* dgi = (const float*)d_in[3];
    float* out = (float*)d_out;

    factorize<<<1, 32>>>(k0, k1, dgi);

    dim3 g1(3, HH, BB);
    dim3 g2(24, 4, BB);
    // sigma 0 (7x7, R=3): strips of 49 = 7*7
    stage1<3><<<g1, 256>>>(in, 0);
    stage2<3, 49, 7><<<g2, 256>>>(0);
    // sigma 1 (13x13, R=6): strips of 52 = 4*13 — reuses g_X scratch
    stage1<6><<<g1, 256>>>(in, 1);
    stage2<6, 52, 4><<<g2, 256>>>(1);

    stage3<<<dim3(12, 12, BB), 256>>>(out);
}

// round 7
// speedup vs baseline: 1.1272x; 1.1272x over previous
#include <cuda_runtime.h>
#include <math.h>

#define BB 4
#define HH 192
#define WW 192
#define CC 64
#define HO 186
#define BHW (BB*HH*WW)          /* 147456 */
#define NELEM (BB*HH*WW*CC)     /* 9437184 */

// ---------------- scratch (device globals; no allocs allowed) ----------------
__device__ __align__(256) float g_X[3][NELEM]; // x-conv results, orders 0..2
__device__ float  g_P[2*10*BHW];   // [(sigma*10+e)][b*H*W] channel-reduced products
__device__ float2 g_fxe[2][7];     // x-factors folded: (ord0, ord2) taps 0..R (R = center)
__device__ float  g_fxo[2][6];     // x-factor order1 taps 0..R-1 (antisym; center==0)
__device__ float4 g_fe[2][7];      // y-factors even maps: (L0=m0, L3=m3, L2=m2, L5=m5)
__device__ float2 g_fo[2][6];      // y-factors odd  maps: (L1=m1, L4=m4)
__device__ float  g_wy[7];         // integrator y factor
__device__ float  g_wx[7];         // integrator x factor

// ---------------- factorization of the 2-D kernels into 1-D factors ----------
__device__ void factor_one(const float* K, int Ksz, int s) {
    const int R = (Ksz - 1) / 2;
    const int canon[3] = {0, 2, 5};          // canonical kernel per x-order (k=0,1,2)
    const int kxo[6]   = {0, 0, 1, 0, 1, 2}; // x-order of kernel m
    int   c0s[3];
    float fx[3][13];
    for (int o = 0; o < 3; ++o) {
        const float* Km = K + canon[o]*Ksz*Ksz*CC;
        int r0 = 0, c0 = 0; float best = -1.f;
        for (int i = 0; i < Ksz; ++i)
            for (int j = 0; j < Ksz; ++j) {
                float v = fabsf(Km[(i*Ksz + j)*CC]);
                if (v > best) { best = v; r0 = i; c0 = j; }
            }
        float piv = Km[(r0*Ksz + c0)*CC];
        for (int j = 0; j < Ksz; ++j) fx[o][j] = Km[(r0*Ksz + j)*CC] / piv;
        c0s[o] = c0;
    }
    for (int t = 0; t <= R; ++t) g_fxe[s][t] = make_float2(fx[0][t], fx[2][t]);
    for (int t = 0; t <  R; ++t) g_fxo[s][t] = fx[1][t];

    const float comb[6] = {1.f, 1.f, 1.f, 1.f, 1.41421356237309515f, 1.f}; // sqrt(C(j,k))
    float fy[6][13];
    for (int m = 0; m < 6; ++m) {
        int c0 = c0s[kxo[m]];
        for (int i = 0; i < Ksz; ++i)
            fy[m][i] = K[(m*Ksz*Ksz + i*Ksz + c0)*CC] * comb[m];
    }
    // evens in y: m0(L0), m3(L3), m2(L2), m5(L5); odds: m1(L1), m4(L4)
    for (int t = 0; t <= R; ++t)
        g_fe[s][t] = make_float4(fy[0][t], fy[3][t], fy[2][t], fy[5][t]);
    for (int t = 0; t <  R; ++t)
        g_fo[s][t] = make_float2(fy[1][t], fy[4][t]);
}

__global__ void factorize(const float* __restrict__ k0, const float* __restrict__ k1,
                          const float* __restrict__ dgi) {
    if (threadIdx.x != 0) return;
    factor_one(k0, 7, 0);
    factor_one(k1, 13, 1);
    // integrator: 7x7 rank-1, all channels identical (take c=0)
    int r0 = 0, c0 = 0; float best = -1.f;
    for (int i = 0; i < 7; ++i)
        for (int j = 0; j < 7; ++j) {
            float v = fabsf(dgi[(i*7 + j)*CC]);
            if (v > best) { best = v; r0 = i; c0 = j; }
        }
    float piv = dgi[(r0*7 + c0)*CC];
    for (int i = 0; i < 7; ++i) g_wy[i] = dgi[(i*7 + c0)*CC];
    for (int j = 0; j < 7; ++j) g_wx[j] = dgi[(r0*7 + j)*CC] / piv;
}

// ---------------- stage 1: horizontal (x) convolution, orders 0..2 ----------
// Thread handles a float2 channel pair; symmetry folds 2K+1 taps into R sums/diffs.
template<int R>
__global__ void __launch_bounds__(256) stage1(const float* __restrict__ in, int sigma) {
    constexpr int K  = 2*R + 1;
    constexpr int XT = 64;
    __shared__ float2 s_in[(XT + 2*R)*32];
    const int b = blockIdx.z, yrow = blockIdx.y, x0 = blockIdx.x*XT;
    const int tid = threadIdx.x;
    const float2* rowv = (const float2*)(in + ((size_t)(b*HH + yrow)*WW)*CC);
    for (int t = tid; t < (XT + 2*R)*32; t += 256) {
        int xx = (t >> 5) - R + x0;
        int c2 = t & 31;
        s_in[t] = (xx >= 0 && xx < WW) ? rowv[xx*32 + c2] : make_float2(0.f, 0.f);
    }
    float2 fxe[R+1]; float fxo[R];
    #pragma unroll
    for (int t = 0; t <= R; ++t) fxe[t] = g_fxe[sigma][t];
    #pragma unroll
    for (int t = 0; t <  R; ++t) fxo[t] = g_fxo[sigma][t];
    __syncthreads();

    const int c2 = tid & 31, xg = tid >> 5;
    const size_t obase = ((size_t)(b*HH + yrow)*WW)*CC;
    float2* o0 = (float2*)&g_X[0][obase];
    float2* o1 = (float2*)&g_X[1][obase];
    float2* o2 = (float2*)&g_X[2][obase];
    #pragma unroll
    for (int xq = 0; xq < 8; ++xq) {
        int xi = xg*8 + xq;
        float2 a0 = {0.f,0.f}, a1 = {0.f,0.f}, a2 = {0.f,0.f};
        #pragma unroll
        for (int t = 0; t < R; ++t) {
            float2 u = s_in[(xi + t)*32 + c2];
            float2 v = s_in[(xi + K - 1 - t)*32 + c2];
            float sx = u.x + v.x, sy = u.y + v.y;
            float dx = u.x - v.x, dy = u.y - v.y;
            a0.x = fmaf(fxe[t].x, sx, a0.x); a0.y = fmaf(fxe[t].x, sy, a0.y);
            a2.x = fmaf(fxe[t].y, sx, a2.x); a2.y = fmaf(fxe[t].y, sy, a2.y);
            a1.x = fmaf(fxo[t],   dx, a1.x); a1.y = fmaf(fxo[t],   dy, a1.y);
        }
        float2 m = s_in[(xi + R)*32 + c2];
        a0.x = fmaf(fxe[R].x, m.x, a0.x); a0.y = fmaf(fxe[R].x, m.y, a0.y);
        a2.x = fmaf(fxe[R].y, m.x, a2.x); a2.y = fmaf(fxe[R].y, m.y, a2.y);
        int off = (x0 + xi)*32 + c2;
        o0[off] = a0; o1[off] = a1; o2[off] = a2;
    }
}

// ---- stage 2: vertical conv (6 L maps) + outer products + channel reduce ----
// Warp = one x column, all 64 channels (2 per lane via float2). Register ring
// over y with unroll-by-K; split-butterfly reduces 10 entries in ~44 instrs,
// leaving entry totals distributed across lanes -> one predicated STG.
template<int R, int SEGH, int NCH>
__global__ void __launch_bounds__(256) stage2(int sigma) {
    constexpr int K = 2*R + 1;
    static_assert(SEGH == NCH*K, "strip must be multiple of K");
    const int tid  = threadIdx.x;
    const int warp = tid >> 5, lane = tid & 31;
    const int b    = blockIdx.z;
    const int x    = blockIdx.x*8 + warp;
    const int ys   = blockIdx.y*SEGH;          // SEGH % K == 0 -> slots compile-time
    const int rs   = WW*32;                    // row stride in float2 units
    const size_t base = ((size_t)(b*HH*WW) + x)*32 + lane;
    const float2* X0 = (const float2*)g_X[0] + base;
    const float2* X1 = (const float2*)g_X[1] + base;
    const float2* X2 = (const float2*)g_X[2] + base;

    float4 fe[R+1]; float2 fo[R];
    #pragma unroll
    for (int t = 0; t <= R; ++t) fe[t] = g_fe[sigma][t];
    #pragma unroll
    for (int t = 0; t <  R; ++t) fo[t] = g_fo[sigma][t];

    // --- per-lane reduction routing (computed once) ---
    const bool h4 = (lane & 16) != 0;
    const bool h3 = (lane & 8)  != 0;
    const bool h2 = (lane & 4)  != 0;
    const bool h1 = (lane & 2)  != 0;
    const bool two = (!h3) && (!h2);           // class holding 2 entries at L3
    const int  m4 = lane & 15;
    const int  f  = (m4==0) ? 0 : (m4==2) ? 1 : (m4==4) ? 2 : (m4==8) ? 3 : 4;
    const int  eidx = (h4 ? 5 : 0) + f;
    const bool writer = (m4==0 || m4==2 || m4==4 || m4==8 || m4==12);
    float* PbE = &g_P[(size_t)(sigma*10 + eidx)*BHW + (size_t)b*HH*WW + x];

    const float2 Z2 = make_float2(0.f, 0.f);
    float2 r0[K], r1[K], r2[K];
    #pragma unroll
    for (int j = 0; j < K - 1; ++j) {            // preload rows ys-R+j
        int yy = ys - R + j;
        const int sl = (j + K - R) % K;
        bool ok = (yy >= 0 && yy < HH);
        r0[sl] = ok ? X0[(size_t)yy*rs] : Z2;
        r1[sl] = ok ? X1[(size_t)yy*rs] : Z2;
        r2[sl] = ok ? X2[(size_t)yy*rs] : Z2;
    }

    int y = ys;
    for (int ch = 0; ch < NCH; ++ch) {
        #pragma unroll
        for (int i = 0; i < K; ++i, ++y) {
            {   // load row y+R into slot (i+R)%K
                const int slN = (i + R) % K;
                int yy = y + R;
                bool ok = yy < HH;
                r0[slN] = ok ? X0[(size_t)yy*rs] : Z2;
                r1[slN] = ok ? X1[(size_t)yy*rs] : Z2;
                r2[slN] = ok ? X2[(size_t)yy*rs] : Z2;
            }
            float2 L0=Z2, L1=Z2, L2=Z2, L3=Z2, L4=Z2, L5=Z2;
            #pragma unroll
            for (int j = 0; j < R; ++j) {
                const int sa = (i + j + (K - R)) % K;
                const int sb = (i + (K - 1 - j) + (K - R)) % K;
                float2 a0 = r0[sa], b0 = r0[sb];
                float2 a1 = r1[sa], b1 = r1[sb];
                float2 a2 = r2[sa], b2 = r2[sb];
                float s0x = a0.x + b0.x, s0y = a0.y + b0.y;
                float d0x = a0.x - b0.x, d0y = a0.y - b0.y;
                float s1x = a1.x + b1.x, s1y = a1.y + b1.y;
                float d1x = a1.x - b1.x, d1y = a1.y - b1.y;
                float s2x = a2.x + b2.x, s2y = a2.y + b2.y;
                L0.x = fmaf(fe[j].x, s0x, L0.x); L0.y = fmaf(fe[j].x, s0y, L0.y);
                L3.x = fmaf(fe[j].y, s0x, L3.x); L3.y = fmaf(fe[j].y, s0y, L3.y);
                L2.x = fmaf(fe[j].z, s1x, L2.x); L2.y = fmaf(fe[j].z, s1y, L2.y);
                L5.x = fmaf(fe[j].w, s2x, L5.x); L5.y = fmaf(fe[j].w, s2y, L5.y);
                L1.x = fmaf(fo[j].x, d0x, L1.x); L1.y = fmaf(fo[j].x, d0y, L1.y);
                L4.x = fmaf(fo[j].y, d1x, L4.x); L4.y = fmaf(fo[j].y, d1y, L4.y);
            }
            {   // center tap: slot == i  (odd maps have exact zero center)
                L0.x = fmaf(fe[R].x, r0[i].x, L0.x); L0.y = fmaf(fe[R].x, r0[i].y, L0.y);
                L3.x = fmaf(fe[R].y, r0[i].x, L3.x); L3.y = fmaf(fe[R].y, r0[i].y, L3.y);
                L2.x = fmaf(fe[R].z, r1[i].x, L2.x); L2.y = fmaf(fe[R].z, r1[i].y, L2.y);
                L5.x = fmaf(fe[R].w, r2[i].x, L5.x); L5.y = fmaf(fe[R].w, r2[i].y, L5.y);
            }
            // per-lane products (2 channels folded)
            float p0 = fmaf(L0.y, L0.y, L0.x*L0.x);
            float p1 = fmaf(L1.y, L1.y, L1.x*L1.x);
            float p2 = fmaf(L1.y, L2.y, L1.x*L2.x);
            float p3 = fmaf(L2.y, L2.y, L2.x*L2.x);
            float p4 = fmaf(L3.y, L3.y, L3.x*L3.x);
            float p5 = fmaf(L3.y, L4.y, L3.x*L4.x);
            float p6 = fmaf(L3.y, L5.y, L3.x*L5.x);
            float p7 = fmaf(L4.y, L4.y, L4.x*L4.x);
            float p8 = fmaf(L4.y, L5.y, L4.x*L5.x);
            float p9 = fmaf(L5.y, L5.y, L5.x*L5.x);

            // --- split-butterfly: 10 entries, halving entry set each level ---
            float v0, v1, v2, v3, v4;
            {
                float q, t;
                q = h4 ? p0 : p5; t = __shfl_xor_sync(0xffffffffu, q, 16); v0 = (h4 ? p5 : p0) + t;
                q = h4 ? p1 : p6; t = __shfl_xor_sync(0xffffffffu, q, 16); v1 = (h4 ? p6 : p1) + t;
                q = h4 ? p2 : p7; t = __shfl_xor_sync(0xffffffffu, q, 16); v2 = (h4 ? p7 : p2) + t;
                q = h4 ? p3 : p8; t = __shfl_xor_sync(0xffffffffu, q, 16); v3 = (h4 ? p8 : p3) + t;
                q = h4 ? p4 : p9; t = __shfl_xor_sync(0xffffffffu, q, 16); v4 = (h4 ? p9 : p4) + t;
            }
            float w0, w1, w2;
            {
                float q0 = h3 ? v0 : v3;
                float q1 = h3 ? v1 : v4;
                float q2 = v2;
                float t0 = __shfl_xor_sync(0xffffffffu, q0, 8);
                float t1 = __shfl_xor_sync(0xffffffffu, q1, 8);
                float t2 = __shfl_xor_sync(0xffffffffu, q2, 8);
                if (!h3) { w0 = v0 + t0; w1 = v1 + t1; w2 = v2 + t2; }
                else     { w0 = v3 + t0; w1 = v4 + t1; w2 = 0.f; }
            }
            float u0, u1;
            {
                float q0 = h2 ? w0 : (h3 ? w1 : w2);
                float q1 = w1;
                float t0 = __shfl_xor_sync(0xffffffffu, q0, 4);
                float t1 = __shfl_xor_sync(0xffffffffu, q1, 4);
                if (!h3) {
                    if (!h2) { u0 = w0 + t0; u1 = w1 + t1; }
                    else     { u0 = w2 + t0; u1 = 0.f; }
                } else {
                    u0 = (h2 ? w1 : w0) + t0; u1 = 0.f;
                }
            }
            float z;
            {
                float q = two ? (h1 ? u0 : u1) : u0;
                float t = __shfl_xor_sync(0xffffffffu, q, 2);
                z = (two ? (h1 ? u1 : u0) : u0) + t;
            }
            z += __shfl_xor_sync(0xffffffffu, z, 1);

            if (writer && y < HH)
                PbE[y*WW] = z;
        }
    }
}

// ------- stage 3: separable 7x7 VALID integration + Newton-identity ESPs ----
// Integrator is rank-1 (wy ⊗ wx): two-pass conv in smem, 10 maps per chunk.
__global__ void __launch_bounds__(256) stage3(float* __restrict__ out) {
    __shared__ float sP[10*22*22];
    __shared__ float sQ[10*22*16];
    const int tid = threadIdx.x;
    const int b = blockIdx.z;
    const int y0 = blockIdx.y*16, x0 = blockIdx.x*16;
    const int ty = tid >> 4, tx = tid & 15;
    const int yo = y0 + ty, xo = x0 + tx;
    const bool inb = (yo < HO) && (xo < HO);

    float wy[7], wx[7];
    #pragma unroll
    for (int i = 0; i < 7; ++i) { wy[i] = g_wy[i]; wx[i] = g_wx[i]; }

    float M[20];
    #pragma unroll
    for (int chunk = 0; chunk < 2; ++chunk) {
        // load 10 maps' 22x22 tiles
        for (int idx = tid; idx < 10*484; idx += 256) {
            int se  = idx / 484;
            int rem = idx - se*484;
            int r   = rem / 22;
            int cc2 = rem - r*22;
            int y = y0 + r, x = x0 + cc2;
            float v = 0.f;
            if (y < HH && x < WW)
                v = g_P[(size_t)(chunk*10 + se)*BHW + (size_t)(b*HH + y)*WW + x];
            sP[idx] = v;
        }
        __syncthreads();
        // pass 1: horizontal (x) conv 22x22 -> 22x16
        for (int idx = tid; idx < 10*352; idx += 256) {
            int se  = idx / 352;
            int rem = idx - se*352;
            int r   = rem >> 4;
            int cx  = rem & 15;
            const float* row = &sP[se*484 + r*22 + cx];
            float a = 0.f;
            #pragma unroll
            for (int j = 0; j < 7; ++j) a = fmaf(wx[j], row[j], a);
            sQ[idx] = a;
        }
        __syncthreads();
        // pass 2: vertical (y) conv 22x16 -> 16x16 (each thread its own output)
        #pragma unroll
        for (int s = 0; s < 10; ++s) {
            float a = 0.f;
            const float* col = &sQ[s*352 + ty*16 + tx];
            #pragma unroll
            for (int i = 0; i < 7; ++i) a = fmaf(wy[i], col[i*16], a);
            M[chunk*10 + s] = a;
        }
        __syncthreads();
    }
    if (!inb) return;

    const float EPSF = 2.2204460492503131e-16f;
    float res[12];
    #pragma unroll
    for (int s = 0; s < 2; ++s) {
        const float* Ms = M + s*10;
        res[s*6 + 0] = fabsf(Ms[0]) + EPSF;
        {
            float a = Ms[1], bq = Ms[2], c2v = Ms[3];
            float p1 = a + c2v;
            float p2 = a*a + 2.f*bq*bq + c2v*c2v;
            float e1 = p1;
            float e2 = 0.5f*(p1*e1 - p2);
            res[s*6 + 1] = 10.f*(fabsf(e1) + EPSF);
            res[s*6 + 2] = 10.f*sqrtf(fabsf(e2) + EPSF);
        }
        {
            float a = Ms[4], bq = Ms[5], cq = Ms[6], d = Ms[7], e = Ms[8], f = Ms[9];
            float p1 = a + d + f;
            float p2 = a*a + d*d + f*f + 2.f*(bq*bq + cq*cq + e*e);
            float p3 = a*a*a + d*d*d + f*f*f
                     + 3.f*(a*(bq*bq + cq*cq) + d*(bq*bq + e*e) + f*(cq*cq + e*e))
                     + 6.f*bq*cq*e;
            float e1 = p1;
            float e2 = 0.5f*(p1*e1 - p2);
            float e3 = (p1*e2 - p2*e1 + p3)*(1.f/3.f);
            res[s*6 + 3] = 100.f*(fabsf(e1) + EPSF);
            res[s*6 + 4] = 100.f*sqrtf(fabsf(e2) + EPSF);
            res[s*6 + 5] = 100.f*cbrtf(fabsf(e3) + EPSF);
        }
    }
    float* op = out + ((size_t)(b*HO + yo)*HO + xo)*12;
    #pragma unroll
    for (int chn = 0; chn < 12; ++chn) op[chn] = res[chn];
}

// ---------------- launcher ---------------------------------------------------
extern "C" void kernel_launch(void* const* d_in, const int* in_sizes, int n_in,
                              void* d_out, int out_size) {
    const float* in  = (const float*)d_in[0];
    const float* k0  = (const float*)d_in[1];
    const float* k1  = (const float*)d_in[2];
    const float* dgi = (const float*)d_in[3];
    float* out = (float*)d_out;

    factorize<<<1, 32>>>(k0, k1, dgi);

    dim3 g1(3, HH, BB);
    dim3 g2(24, 4, BB);
    // sigma 0 (7x7, R=3): strips of 49 = 7*7
    stage1<3><<<g1, 256>>>(in, 0);
    stage2<3, 49, 7><<<g2, 256>>>(0);
    // sigma 1 (13x13, R=6): strips of 52 = 4*13 — reuses g_X scratch
    stage1<6><<<g1, 256>>>(in, 1);
    stage2<6, 52, 4><<<g2, 256>>>(1);

    stage3<<<dim3(12, 12, BB), 256>>>(out);
}

// round 8
// speedup vs baseline: 1.3387x; 1.1877x over previous
#include <cuda_runtime.h>
#include <math.h>

#define BB 4
#define HH 192
#define WW 192
#define CC 64
#define HO 186
#define BHW (BB*HH*WW)          /* 147456 */
#define NELEM (BB*HH*WW*CC)     /* 9437184 */

// ---------------- scratch (device globals; no allocs allowed) ----------------
__device__ __align__(256) float g_X[3][NELEM]; // x-conv results, orders 0..2
__device__ float  g_P[2*10*BHW];   // [(sigma*10+e)][b*H*W] channel-reduced products
__device__ float2 g_fxe[2][7];     // x-factors folded: (ord0, ord2) taps 0..R (R = center)
__device__ float  g_fxo[2][6];     // x-factor order1 taps 0..R-1 (antisym; center==0)
__device__ float4 g_fe[2][7];      // y-factors even maps: (L0=m0, L3=m3, L2=m2, L5=m5)
__device__ float2 g_fo[2][6];      // y-factors odd  maps: (L1=m1, L4=m4)
__device__ float  g_wy[7];         // integrator y factor
__device__ float  g_wx[7];         // integrator x factor

// -------- factorization: parallel load to smem, warp argmax, tiny serial tail
__global__ void __launch_bounds__(256) factorize(const float* __restrict__ k0,
                                                 const float* __restrict__ k1,
                                                 const float* __restrict__ dgi) {
    __shared__ float sk[294 + 1014 + 49];
    __shared__ int   s_r0[7], s_c0[7];
    __shared__ float s_piv[7];
    float* sk0 = sk;
    float* sk1 = sk + 294;
    float* sdg = sk + 294 + 1014;
    const int tid = threadIdx.x;
    // stage channel-0 planes of all kernels into smem (parallel LDG)
    for (int i = tid; i < 294;  i += 256) sk0[i] = k0[(size_t)i*CC];
    for (int i = tid; i < 1014; i += 256) sk1[i] = k1[(size_t)i*CC];
    for (int i = tid; i < 49;   i += 256) sdg[i] = dgi[(size_t)i*CC];
    __syncthreads();

    // 7 pivot searches: warps 0-2 -> k0 canon {0,2,5}; 3-5 -> k1 canon; 6 -> dgi
    const int warp = tid >> 5, lane = tid & 31;
    const int canon[3] = {0, 2, 5};
    if (warp < 7) {
        const float* base; int Ksz, n;
        if (warp < 3)      { base = sk0 + canon[warp]*49;        Ksz = 7;  n = 49;  }
        else if (warp < 6) { base = sk1 + canon[warp - 3]*169;   Ksz = 13; n = 169; }
        else               { base = sdg;                          Ksz = 7;  n = 49;  }
        float best = -1.f; int bidx = 0;
        for (int i = lane; i < n; i += 32) {
            float v = fabsf(base[i]);
            if (v > best) { best = v; bidx = i; }
        }
        #pragma unroll
        for (int off = 16; off >= 1; off >>= 1) {
            float ob = __shfl_xor_sync(0xffffffffu, best, off);
            int   oi = __shfl_xor_sync(0xffffffffu, bidx, off);
            if (ob > best || (ob == best && oi < bidx)) { best = ob; bidx = oi; }
        }
        if (lane == 0) {
            s_r0[warp] = bidx / Ksz; s_c0[warp] = bidx % Ksz; s_piv[warp] = base[bidx];
        }
    }
    __syncthreads();

    if (tid != 0) return;
    const int kxo[6]  = {0, 0, 1, 0, 1, 2};
    const float comb[6] = {1.f, 1.f, 1.f, 1.f, 1.41421356237309515f, 1.f};
    for (int s = 0; s < 2; ++s) {
        const float* skb = s ? sk1 : sk0;
        const int Ksz = s ? 13 : 7, R = (Ksz - 1)/2, per = Ksz*Ksz;
        float fx[3][13]; int c0s[3];
        for (int o = 0; o < 3; ++o) {
            const int task = s*3 + o;
            const int r0 = s_r0[task]; c0s[o] = s_c0[task];
            const float piv = s_piv[task];
            const float* Km = skb + canon[o]*per;
            for (int j = 0; j < Ksz; ++j) fx[o][j] = Km[r0*Ksz + j] / piv;
        }
        for (int t = 0; t <= R; ++t) g_fxe[s][t] = make_float2(fx[0][t], fx[2][t]);
        for (int t = 0; t <  R; ++t) g_fxo[s][t] = fx[1][t];
        float fy[6][13];
        for (int m = 0; m < 6; ++m) {
            const int c0 = c0s[kxo[m]];
            for (int i = 0; i < Ksz; ++i) fy[m][i] = skb[m*per + i*Ksz + c0] * comb[m];
        }
        for (int t = 0; t <= R; ++t)
            g_fe[s][t] = make_float4(fy[0][t], fy[3][t], fy[2][t], fy[5][t]);
        for (int t = 0; t <  R; ++t)
            g_fo[s][t] = make_float2(fy[1][t], fy[4][t]);
    }
    { // integrator (task 6)
        const int r0 = s_r0[6], c0 = s_c0[6]; const float piv = s_piv[6];
        for (int i = 0; i < 7; ++i) g_wy[i] = sdg[i*7 + c0];
        for (int j = 0; j < 7; ++j) g_wx[j] = sdg[r0*7 + j] / piv;
    }
}

// ---------------- stage 1: horizontal (x) convolution, orders 0..2 ----------
// Thread handles a float2 channel pair; symmetry folds 2K+1 taps into R sums/diffs.
template<int R>
__global__ void __launch_bounds__(256) stage1(const float* __restrict__ in, int sigma) {
    constexpr int K  = 2*R + 1;
    constexpr int XT = 64;
    __shared__ float2 s_in[(XT + 2*R)*32];
    const int b = blockIdx.z, yrow = blockIdx.y, x0 = blockIdx.x*XT;
    const int tid = threadIdx.x;
    const float2* rowv = (const float2*)(in + ((size_t)(b*HH + yrow)*WW)*CC);
    for (int t = tid; t < (XT + 2*R)*32; t += 256) {
        int xx = (t >> 5) - R + x0;
        int c2 = t & 31;
        s_in[t] = (xx >= 0 && xx < WW) ? rowv[xx*32 + c2] : make_float2(0.f, 0.f);
    }
    float2 fxe[R+1]; float fxo[R];
    #pragma unroll
    for (int t = 0; t <= R; ++t) fxe[t] = g_fxe[sigma][t];
    #pragma unroll
    for (int t = 0; t <  R; ++t) fxo[t] = g_fxo[sigma][t];
    __syncthreads();

    const int c2 = tid & 31, xg = tid >> 5;
    const size_t obase = ((size_t)(b*HH + yrow)*WW)*CC;
    float2* o0 = (float2*)&g_X[0][obase];
    float2* o1 = (float2*)&g_X[1][obase];
    float2* o2 = (float2*)&g_X[2][obase];
    #pragma unroll
    for (int xq = 0; xq < 8; ++xq) {
        int xi = xg*8 + xq;
        float2 a0 = {0.f,0.f}, a1 = {0.f,0.f}, a2 = {0.f,0.f};
        #pragma unroll
        for (int t = 0; t < R; ++t) {
            float2 u = s_in[(xi + t)*32 + c2];
            float2 v = s_in[(xi + K - 1 - t)*32 + c2];
            float sx = u.x + v.x, sy = u.y + v.y;
            float dx = u.x - v.x, dy = u.y - v.y;
            a0.x = fmaf(fxe[t].x, sx, a0.x); a0.y = fmaf(fxe[t].x, sy, a0.y);
            a2.x = fmaf(fxe[t].y, sx, a2.x); a2.y = fmaf(fxe[t].y, sy, a2.y);
            a1.x = fmaf(fxo[t],   dx, a1.x); a1.y = fmaf(fxo[t],   dy, a1.y);
        }
        float2 m = s_in[(xi + R)*32 + c2];
        a0.x = fmaf(fxe[R].x, m.x, a0.x); a0.y = fmaf(fxe[R].x, m.y, a0.y);
        a2.x = fmaf(fxe[R].y, m.x, a2.x); a2.y = fmaf(fxe[R].y, m.y, a2.y);
        int off = (x0 + xi)*32 + c2;
        o0[off] = a0; o1[off] = a1; o2[off] = a2;
    }
}

// ---- stage 2: vertical conv (6 L maps) + outer products + channel reduce ----
// Warp = one x column, all 64 channels (2 per lane via float2). Register ring
// over y with unroll-by-K; split-butterfly reduces 10 entries in ~44 instrs,
// leaving entry totals distributed across lanes -> one predicated STG.
template<int R, int SEGH, int NCH>
__global__ void __launch_bounds__(256) stage2(int sigma) {
    constexpr int K = 2*R + 1;
    static_assert(SEGH == NCH*K, "strip must be multiple of K");
    const int tid  = threadIdx.x;
    const int warp = tid >> 5, lane = tid & 31;
    const int b    = blockIdx.z;
    const int x    = blockIdx.x*8 + warp;
    const int ys   = blockIdx.y*SEGH;          // SEGH % K == 0 -> slots compile-time
    const int rs   = WW*32;                    // row stride in float2 units
    const size_t base = ((size_t)(b*HH*WW) + x)*32 + lane;
    const float2* X0 = (const float2*)g_X[0] + base;
    const float2* X1 = (const float2*)g_X[1] + base;
    const float2* X2 = (const float2*)g_X[2] + base;

    float4 fe[R+1]; float2 fo[R];
    #pragma unroll
    for (int t = 0; t <= R; ++t) fe[t] = g_fe[sigma][t];
    #pragma unroll
    for (int t = 0; t <  R; ++t) fo[t] = g_fo[sigma][t];

    // --- per-lane reduction routing (computed once) ---
    const bool h4 = (lane & 16) != 0;
    const bool h3 = (lane & 8)  != 0;
    const bool h2 = (lane & 4)  != 0;
    const bool h1 = (lane & 2)  != 0;
    const bool two = (!h3) && (!h2);           // class holding 2 entries at L3
    const int  m4 = lane & 15;
    const int  f  = (m4==0) ? 0 : (m4==2) ? 1 : (m4==4) ? 2 : (m4==8) ? 3 : 4;
    const int  eidx = (h4 ? 5 : 0) + f;
    const bool writer = (m4==0 || m4==2 || m4==4 || m4==8 || m4==12);
    float* PbE = &g_P[(size_t)(sigma*10 + eidx)*BHW + (size_t)b*HH*WW + x];

    const float2 Z2 = make_float2(0.f, 0.f);
    float2 r0[K], r1[K], r2[K];
    #pragma unroll
    for (int j = 0; j < K - 1; ++j) {            // preload rows ys-R+j
        int yy = ys - R + j;
        const int sl = (j + K - R) % K;
        bool ok = (yy >= 0 && yy < HH);
        r0[sl] = ok ? X0[(size_t)yy*rs] : Z2;
        r1[sl] = ok ? X1[(size_t)yy*rs] : Z2;
        r2[sl] = ok ? X2[(size_t)yy*rs] : Z2;
    }

    int y = ys;
    for (int ch = 0; ch < NCH; ++ch) {
        #pragma unroll
        for (int i = 0; i < K; ++i, ++y) {
            {   // load row y+R into slot (i+R)%K
                const int slN = (i + R) % K;
                int yy = y + R;
                bool ok = yy < HH;
                r0[slN] = ok ? X0[(size_t)yy*rs] : Z2;
                r1[slN] = ok ? X1[(size_t)yy*rs] : Z2;
                r2[slN] = ok ? X2[(size_t)yy*rs] : Z2;
            }
            float2 L0=Z2, L1=Z2, L2=Z2, L3=Z2, L4=Z2, L5=Z2;
            #pragma unroll
            for (int j = 0; j < R; ++j) {
                const int sa = (i + j + (K - R)) % K;
                const int sb = (i + (K - 1 - j) + (K - R)) % K;
                float2 a0 = r0[sa], b0 = r0[sb];
                float2 a1 = r1[sa], b1 = r1[sb];
                float2 a2 = r2[sa], b2 = r2[sb];
                float s0x = a0.x + b0.x, s0y = a0.y + b0.y;
                float d0x = a0.x - b0.x, d0y = a0.y - b0.y;
                float s1x = a1.x + b1.x, s1y = a1.y + b1.y;
                float d1x = a1.x - b1.x, d1y = a1.y - b1.y;
                float s2x = a2.x + b2.x, s2y = a2.y + b2.y;
                L0.x = fmaf(fe[j].x, s0x, L0.x); L0.y = fmaf(fe[j].x, s0y, L0.y);
                L3.x = fmaf(fe[j].y, s0x, L3.x); L3.y = fmaf(fe[j].y, s0y, L3.y);
                L2.x = fmaf(fe[j].z, s1x, L2.x); L2.y = fmaf(fe[j].z, s1y, L2.y);
                L5.x = fmaf(fe[j].w, s2x, L5.x); L5.y = fmaf(fe[j].w, s2y, L5.y);
                L1.x = fmaf(fo[j].x, d0x, L1.x); L1.y = fmaf(fo[j].x, d0y, L1.y);
                L4.x = fmaf(fo[j].y, d1x, L4.x); L4.y = fmaf(fo[j].y, d1y, L4.y);
            }
            {   // center tap: slot == i  (odd maps have exact zero center)
                L0.x = fmaf(fe[R].x, r0[i].x, L0.x); L0.y = fmaf(fe[R].x, r0[i].y, L0.y);
                L3.x = fmaf(fe[R].y, r0[i].x, L3.x); L3.y = fmaf(fe[R].y, r0[i].y, L3.y);
                L2.x = fmaf(fe[R].z, r1[i].x, L2.x); L2.y = fmaf(fe[R].z, r1[i].y, L2.y);
                L5.x = fmaf(fe[R].w, r2[i].x, L5.x); L5.y = fmaf(fe[R].w, r2[i].y, L5.y);
            }
            // per-lane products (2 channels folded)
            float p0 = fmaf(L0.y, L0.y, L0.x*L0.x);
            float p1 = fmaf(L1.y, L1.y, L1.x*L1.x);
            float p2 = fmaf(L1.y, L2.y, L1.x*L2.x);
            float p3 = fmaf(L2.y, L2.y, L2.x*L2.x);
            float p4 = fmaf(L3.y, L3.y, L3.x*L3.x);
            float p5 = fmaf(L3.y, L4.y, L3.x*L4.x);
            float p6 = fmaf(L3.y, L5.y, L3.x*L5.x);
            float p7 = fmaf(L4.y, L4.y, L4.x*L4.x);
            float p8 = fmaf(L4.y, L5.y, L4.x*L5.x);
            float p9 = fmaf(L5.y, L5.y, L5.x*L5.x);

            // --- split-butterfly: 10 entries, halving entry set each level ---
            float v0, v1, v2, v3, v4;
            {
                float q, t;
                q = h4 ? p0 : p5; t = __shfl_xor_sync(0xffffffffu, q, 16); v0 = (h4 ? p5 : p0) + t;
                q = h4 ? p1 : p6; t = __shfl_xor_sync(0xffffffffu, q, 16); v1 = (h4 ? p6 : p1) + t;
                q = h4 ? p2 : p7; t = __shfl_xor_sync(0xffffffffu, q, 16); v2 = (h4 ? p7 : p2) + t;
                q = h4 ? p3 : p8; t = __shfl_xor_sync(0xffffffffu, q, 16); v3 = (h4 ? p8 : p3) + t;
                q = h4 ? p4 : p9; t = __shfl_xor_sync(0xffffffffu, q, 16); v4 = (h4 ? p9 : p4) + t;
            }
            float w0, w1, w2;
            {
                float q0 = h3 ? v0 : v3;
                float q1 = h3 ? v1 : v4;
                float q2 = v2;
                float t0 = __shfl_xor_sync(0xffffffffu, q0, 8);
                float t1 = __shfl_xor_sync(0xffffffffu, q1, 8);
                float t2 = __shfl_xor_sync(0xffffffffu, q2, 8);
                if (!h3) { w0 = v0 + t0; w1 = v1 + t1; w2 = v2 + t2; }
                else     { w0 = v3 + t0; w1 = v4 + t1; w2 = 0.f; }
            }
            float u0, u1;
            {
                float q0 = h2 ? w0 : (h3 ? w1 : w2);
                float q1 = w1;
                float t0 = __shfl_xor_sync(0xffffffffu, q0, 4);
                float t1 = __shfl_xor_sync(0xffffffffu, q1, 4);
                if (!h3) {
                    if (!h2) { u0 = w0 + t0; u1 = w1 + t1; }
                    else     { u0 = w2 + t0; u1 = 0.f; }
                } else {
                    u0 = (h2 ? w1 : w0) + t0; u1 = 0.f;
                }
            }
            float z;
            {
                float q = two ? (h1 ? u0 : u1) : u0;
                float t = __shfl_xor_sync(0xffffffffu, q, 2);
                z = (two ? (h1 ? u1 : u0) : u0) + t;
            }
            z += __shfl_xor_sync(0xffffffffu, z, 1);

            if (writer && y < HH)
                PbE[y*WW] = z;
        }
    }
}

// ------- stage 3: separable 7x7 VALID integration + Newton-identity ESPs ----
// Integrator is rank-1 (wy ⊗ wx): two-pass conv in smem, 10 maps per chunk.
__global__ void __launch_bounds__(256) stage3(float* __restrict__ out) {
    __shared__ float sP[10*22*22];
    __shared__ float sQ[10*22*16];
    const int tid = threadIdx.x;
    const int b = blockIdx.z;
    const int y0 = blockIdx.y*16, x0 = blockIdx.x*16;
    const int ty = tid >> 4, tx = tid & 15;
    const int yo = y0 + ty, xo = x0 + tx;
    const bool inb = (yo < HO) && (xo < HO);

    float wy[7], wx[7];
    #pragma unroll
    for (int i = 0; i < 7; ++i) { wy[i] = g_wy[i]; wx[i] = g_wx[i]; }

    float M[20];
    #pragma unroll
    for (int chunk = 0; chunk < 2; ++chunk) {
        // load 10 maps' 22x22 tiles
        for (int idx = tid; idx < 10*484; idx += 256) {
            int se  = idx / 484;
            int rem = idx - se*484;
            int r   = rem / 22;
            int cc2 = rem - r*22;
            int y = y0 + r, x = x0 + cc2;
            float v = 0.f;
            if (y < HH && x < WW)
                v = g_P[(size_t)(chunk*10 + se)*BHW + (size_t)(b*HH + y)*WW + x];
            sP[idx] = v;
        }
        __syncthreads();
        // pass 1: horizontal (x) conv 22x22 -> 22x16
        for (int idx = tid; idx < 10*352; idx += 256) {
            int se  = idx / 352;
            int rem = idx - se*352;
            int r   = rem >> 4;
            int cx  = rem & 15;
            const float* row = &sP[se*484 + r*22 + cx];
            float a = 0.f;
            #pragma unroll
            for (int j = 0; j < 7; ++j) a = fmaf(wx[j], row[j], a);
            sQ[idx] = a;
        }
        __syncthreads();
        // pass 2: vertical (y) conv 22x16 -> 16x16 (each thread its own output)
        #pragma unroll
        for (int s = 0; s < 10; ++s) {
            float a = 0.f;
            const float* col = &sQ[s*352 + ty*16 + tx];
            #pragma unroll
            for (int i = 0; i < 7; ++i) a = fmaf(wy[i], col[i*16], a);
            M[chunk*10 + s] = a;
        }
        __syncthreads();
    }
    if (!inb) return;

    const float EPSF = 2.2204460492503131e-16f;
    float res[12];
    #pragma unroll
    for (int s = 0; s < 2; ++s) {
        const float* Ms = M + s*10;
        res[s*6 + 0] = fabsf(Ms[0]) + EPSF;
        {
            float a = Ms[1], bq = Ms[2], c2v = Ms[3];
            float p1 = a + c2v;
            float p2 = a*a + 2.f*bq*bq + c2v*c2v;
            float e1 = p1;
            float e2 = 0.5f*(p1*e1 - p2);
            res[s*6 + 1] = 10.f*(fabsf(e1) + EPSF);
            res[s*6 + 2] = 10.f*sqrtf(fabsf(e2) + EPSF);
        }
        {
            float a = Ms[4], bq = Ms[5], cq = Ms[6], d = Ms[7], e = Ms[8], f = Ms[9];
            float p1 = a + d + f;
            float p2 = a*a + d*d + f*f + 2.f*(bq*bq + cq*cq + e*e);
            float p3 = a*a*a + d*d*d + f*f*f
                     + 3.f*(a*(bq*bq + cq*cq) + d*(bq*bq + e*e) + f*(cq*cq + e*e))
                     + 6.f*bq*cq*e;
            float e1 = p1;
            float e2 = 0.5f*(p1*e1 - p2);
            float e3 = (p1*e2 - p2*e1 + p3)*(1.f/3.f);
            res[s*6 + 3] = 100.f*(fabsf(e1) + EPSF);
            res[s*6 + 4] = 100.f*sqrtf(fabsf(e2) + EPSF);
            res[s*6 + 5] = 100.f*cbrtf(fabsf(e3) + EPSF);
        }
    }
    float* op = out + ((size_t)(b*HO + yo)*HO + xo)*12;
    #pragma unroll
    for (int chn = 0; chn < 12; ++chn) op[chn] = res[chn];
}

// ---------------- launcher ---------------------------------------------------
extern "C" void kernel_launch(void* const* d_in, const int* in_sizes, int n_in,
                              void* d_out, int out_size) {
    const float* in  = (const float*)d_in[0];
    const float* k0  = (const float*)d_in[1];
    const float* k1  = (const float*)d_in[2];
    const float* dgi = (const float*)d_in[3];
    float* out = (float*)d_out;

    factorize<<<1, 256>>>(k0, k1, dgi);

    dim3 g1(3, HH, BB);
    // sigma 0 (7x7, R=3): 7 strips of 28 = 4*7
    stage1<3><<<g1, 256>>>(in, 0);
    stage2<3, 28, 4><<<dim3(24, 7, BB), 256>>>(0);
    // sigma 1 (13x13, R=6): 5 strips of 39 = 3*13 — reuses g_X scratch
    stage1<6><<<g1, 256>>>(in, 1);
    stage2<6, 39, 3><<<dim3(24, 5, BB), 256>>>(1);

    stage3<<<dim3(12, 12, BB), 256>>>(out);
}

// round 9
// speedup vs baseline: 1.3893x; 1.0378x over previous
#include <cuda_runtime.h>
#include <math.h>

#define BB 4
#define HH 192
#define WW 192
#define CC 64
#define HO 186
#define BHW (BB*HH*WW)          /* 147456 */
#define NELEM (BB*HH*WW*CC)     /* 9437184 */

// ---------------- scratch (device globals; no allocs allowed) ----------------
__device__ __align__(256) float g_X[6][NELEM]; // x-conv: [sigma*3+order]
__device__ float  g_P[2*10*BHW];   // [(sigma*10+e)][b*H*W] channel-reduced products
__device__ float2 g_fxe[2][7];     // x-factors folded: (ord0, ord2) taps 0..R (R = center)
__device__ float  g_fxo[2][6];     // x-factor order1 taps 0..R-1 (antisym; center==0)
__device__ float4 g_fe[2][7];      // y-factors even maps: (L0=m0, L3=m3, L2=m2, L5=m5)
__device__ float2 g_fo[2][6];      // y-factors odd  maps: (L1=m1, L4=m4)
__device__ float  g_wy[7];         // integrator y factor
__device__ float  g_wx[7];         // integrator x factor

// -------- factorization: parallel load to smem, warp argmax, tiny serial tail
__global__ void __launch_bounds__(256) factorize(const float* __restrict__ k0,
                                                 const float* __restrict__ k1,
                                                 const float* __restrict__ dgi) {
    __shared__ float sk[294 + 1014 + 49];
    __shared__ int   s_r0[7], s_c0[7];
    __shared__ float s_piv[7];
    float* sk0 = sk;
    float* sk1 = sk + 294;
    float* sdg = sk + 294 + 1014;
    const int tid = threadIdx.x;
    for (int i = tid; i < 294;  i += 256) sk0[i] = k0[(size_t)i*CC];
    for (int i = tid; i < 1014; i += 256) sk1[i] = k1[(size_t)i*CC];
    for (int i = tid; i < 49;   i += 256) sdg[i] = dgi[(size_t)i*CC];
    __syncthreads();

    const int warp = tid >> 5, lane = tid & 31;
    const int canon[3] = {0, 2, 5};
    if (warp < 7) {
        const float* base; int Ksz, n;
        if (warp < 3)      { base = sk0 + canon[warp]*49;        Ksz = 7;  n = 49;  }
        else if (warp < 6) { base = sk1 + canon[warp - 3]*169;   Ksz = 13; n = 169; }
        else               { base = sdg;                          Ksz = 7;  n = 49;  }
        float best = -1.f; int bidx = 0;
        for (int i = lane; i < n; i += 32) {
            float v = fabsf(base[i]);
            if (v > best) { best = v; bidx = i; }
        }
        #pragma unroll
        for (int off = 16; off >= 1; off >>= 1) {
            float ob = __shfl_xor_sync(0xffffffffu, best, off);
            int   oi = __shfl_xor_sync(0xffffffffu, bidx, off);
            if (ob > best || (ob == best && oi < bidx)) { best = ob; bidx = oi; }
        }
        if (lane == 0) {
            s_r0[warp] = bidx / Ksz; s_c0[warp] = bidx % Ksz; s_piv[warp] = base[bidx];
        }
    }
    __syncthreads();

    if (tid != 0) return;
    const int kxo[6]  = {0, 0, 1, 0, 1, 2};
    const float comb[6] = {1.f, 1.f, 1.f, 1.f, 1.41421356237309515f, 1.f};
    for (int s = 0; s < 2; ++s) {
        const float* skb = s ? sk1 : sk0;
        const int Ksz = s ? 13 : 7, R = (Ksz - 1)/2, per = Ksz*Ksz;
        float fx[3][13]; int c0s[3];
        for (int o = 0; o < 3; ++o) {
            const int task = s*3 + o;
            const int r0 = s_r0[task]; c0s[o] = s_c0[task];
            const float piv = s_piv[task];
            const float* Km = skb + canon[o]*per;
            for (int j = 0; j < Ksz; ++j) fx[o][j] = Km[r0*Ksz + j] / piv;
        }
        for (int t = 0; t <= R; ++t) g_fxe[s][t] = make_float2(fx[0][t], fx[2][t]);
        for (int t = 0; t <  R; ++t) g_fxo[s][t] = fx[1][t];
        float fy[6][13];
        for (int m = 0; m < 6; ++m) {
            const int c0 = c0s[kxo[m]];
            for (int i = 0; i < Ksz; ++i) fy[m][i] = skb[m*per + i*Ksz + c0] * comb[m];
        }
        for (int t = 0; t <= R; ++t)
            g_fe[s][t] = make_float4(fy[0][t], fy[3][t], fy[2][t], fy[5][t]);
        for (int t = 0; t <  R; ++t)
            g_fo[s][t] = make_float2(fy[1][t], fy[4][t]);
    }
    {
        const int r0 = s_r0[6], c0 = s_c0[6]; const float piv = s_piv[6];
        for (int i = 0; i < 7; ++i) g_wy[i] = sdg[i*7 + c0];
        for (int j = 0; j < 7; ++j) g_wx[j] = sdg[r0*7 + j] / piv;
    }
}

// ------- stage 1 (merged): x-convs for BOTH sigmas, orders 0..2 each --------
// Shared R=6 halo. Sigma0's folded tap t0 uses the same (sum,diff) as sigma1's
// tap t = t0+3, so its taps are free reuses of sigma1's adds.
__global__ void __launch_bounds__(256) stage1_both(const float* __restrict__ in) {
    constexpr int XT = 64;
    __shared__ float2 s_in[(XT + 12)*32];
    const int b = blockIdx.z, yrow = blockIdx.y, x0 = blockIdx.x*XT;
    const int tid = threadIdx.x;
    const float2* rowv = (const float2*)(in + ((size_t)(b*HH + yrow)*WW)*CC);
    for (int t = tid; t < (XT + 12)*32; t += 256) {
        int xx = (t >> 5) - 6 + x0;
        int c2 = t & 31;
        s_in[t] = (xx >= 0 && xx < WW) ? rowv[xx*32 + c2] : make_float2(0.f, 0.f);
    }
    float2 fxe0[4], fxe1[7]; float fxo0[3], fxo1[6];
    #pragma unroll
    for (int t = 0; t < 4; ++t) fxe0[t] = g_fxe[0][t];
    #pragma unroll
    for (int t = 0; t < 3; ++t) fxo0[t] = g_fxo[0][t];
    #pragma unroll
    for (int t = 0; t < 7; ++t) fxe1[t] = g_fxe[1][t];
    #pragma unroll
    for (int t = 0; t < 6; ++t) fxo1[t] = g_fxo[1][t];
    __syncthreads();

    const int c2 = tid & 31, xg = tid >> 5;
    const size_t obase = ((size_t)(b*HH + yrow)*WW)*CC;
    float2* o00 = (float2*)&g_X[0][obase];
    float2* o01 = (float2*)&g_X[1][obase];
    float2* o02 = (float2*)&g_X[2][obase];
    float2* o10 = (float2*)&g_X[3][obase];
    float2* o11 = (float2*)&g_X[4][obase];
    float2* o12 = (float2*)&g_X[5][obase];
    #pragma unroll
    for (int xq = 0; xq < 8; ++xq) {
        int xi = xg*8 + xq;
        float2 A0={0.f,0.f}, A1={0.f,0.f}, A2={0.f,0.f};   // sigma0 maps 0..2
        float2 B0={0.f,0.f}, B1={0.f,0.f}, B2={0.f,0.f};   // sigma1 maps 0..2
        #pragma unroll
        for (int t = 0; t < 6; ++t) {
            float2 u = s_in[(xi + t)*32 + c2];
            float2 v = s_in[(xi + 12 - t)*32 + c2];
            float sx = u.x + v.x, sy = u.y + v.y;
            float dx = u.x - v.x, dy = u.y - v.y;
            B0.x = fmaf(fxe1[t].x, sx, B0.x); B0.y = fmaf(fxe1[t].x, sy, B0.y);
            B2.x = fmaf(fxe1[t].y, sx, B2.x); B2.y = fmaf(fxe1[t].y, sy, B2.y);
            B1.x = fmaf(fxo1[t],   dx, B1.x); B1.y = fmaf(fxo1[t],   dy, B1.y);
            if (t >= 3) {
                const int t0 = t - 3;
                A0.x = fmaf(fxe0[t0].x, sx, A0.x); A0.y = fmaf(fxe0[t0].x, sy, A0.y);
                A2.x = fmaf(fxe0[t0].y, sx, A2.x); A2.y = fmaf(fxe0[t0].y, sy, A2.y);
                A1.x = fmaf(fxo0[t0],   dx, A1.x); A1.y = fmaf(fxo0[t0],   dy, A1.y);
            }
        }
        float2 m = s_in[(xi + 6)*32 + c2];
        B0.x = fmaf(fxe1[6].x, m.x, B0.x); B0.y = fmaf(fxe1[6].x, m.y, B0.y);
        B2.x = fmaf(fxe1[6].y, m.x, B2.x); B2.y = fmaf(fxe1[6].y, m.y, B2.y);
        A0.x = fmaf(fxe0[3].x, m.x, A0.x); A0.y = fmaf(fxe0[3].x, m.y, A0.y);
        A2.x = fmaf(fxe0[3].y, m.x, A2.x); A2.y = fmaf(fxe0[3].y, m.y, A2.y);
        int off = (x0 + xi)*32 + c2;
        o00[off] = A0; o01[off] = A1; o02[off] = A2;
        o10[off] = B0; o11[off] = B1; o12[off] = B2;
    }
}

// ---- stage 2: vertical conv (6 L maps) + outer products + channel reduce ----
// Warp = one x column, all 64 channels (2 per lane via float2). Register ring
// over y with unroll-by-K; loads software-pipelined by one iteration (temps).
// Split-butterfly reduce; one predicated STG.
template<int R, int SEGH, int NCH>
__global__ void __launch_bounds__(256) stage2(int sigma) {
    constexpr int K = 2*R + 1;
    static_assert(SEGH == NCH*K, "strip must be multiple of K");
    const int tid  = threadIdx.x;
    const int warp = tid >> 5, lane = tid & 31;
    const int b    = blockIdx.z;
    const int x    = blockIdx.x*8 + warp;
    const int ys   = blockIdx.y*SEGH;          // SEGH % K == 0 -> slots compile-time
    const int rs   = WW*32;                    // row stride in float2 units
    const size_t base = ((size_t)(b*HH*WW) + x)*32 + lane;
    const float2* X0 = (const float2*)g_X[sigma*3 + 0] + base;
    const float2* X1 = (const float2*)g_X[sigma*3 + 1] + base;
    const float2* X2 = (const float2*)g_X[sigma*3 + 2] + base;

    float4 fe[R+1]; float2 fo[R];
    #pragma unroll
    for (int t = 0; t <= R; ++t) fe[t] = g_fe[sigma][t];
    #pragma unroll
    for (int t = 0; t <  R; ++t) fo[t] = g_fo[sigma][t];

    // --- per-lane reduction routing (computed once) ---
    const bool h4 = (lane & 16) != 0;
    const bool h3 = (lane & 8)  != 0;
    const bool h2 = (lane & 4)  != 0;
    const bool h1 = (lane & 2)  != 0;
    const bool two = (!h3) && (!h2);           // class holding 2 entries at L3
    const int  m4 = lane & 15;
    const int  f  = (m4==0) ? 0 : (m4==2) ? 1 : (m4==4) ? 2 : (m4==8) ? 3 : 4;
    const int  eidx = (h4 ? 5 : 0) + f;
    const bool writer = (m4==0 || m4==2 || m4==4 || m4==8 || m4==12);
    float* PbE = &g_P[(size_t)(sigma*10 + eidx)*BHW + (size_t)b*HH*WW + x];

    const float2 Z2 = make_float2(0.f, 0.f);
    float2 r0[K], r1[K], r2[K];
    #pragma unroll
    for (int j = 0; j < K - 1; ++j) {            // preload rows ys-R+j
        int yy = ys - R + j;
        const int sl = (j + K - R) % K;
        bool ok = (yy >= 0 && yy < HH);
        r0[sl] = ok ? X0[(size_t)yy*rs] : Z2;
        r1[sl] = ok ? X1[(size_t)yy*rs] : Z2;
        r2[sl] = ok ? X2[(size_t)yy*rs] : Z2;
    }
    // prefetch row ys+R into temps (committed at top of first iteration)
    float2 t0, t1, t2;
    {
        int yy = ys + R;
        bool ok = yy < HH;
        t0 = ok ? X0[(size_t)yy*rs] : Z2;
        t1 = ok ? X1[(size_t)yy*rs] : Z2;
        t2 = ok ? X2[(size_t)yy*rs] : Z2;
    }

    int y = ys;
    for (int ch = 0; ch < NCH; ++ch) {
        #pragma unroll
        for (int i = 0; i < K; ++i, ++y) {
            {   // commit prefetched row y+R into slot (i+R)%K
                const int slN = (i + R) % K;
                r0[slN] = t0; r1[slN] = t1; r2[slN] = t2;
            }
            {   // issue prefetch for row y+1+R (consumed next iteration)
                int yy = y + 1 + R;
                bool ok = yy < HH;
                t0 = ok ? X0[(size_t)yy*rs] : Z2;
                t1 = ok ? X1[(size_t)yy*rs] : Z2;
                t2 = ok ? X2[(size_t)yy*rs] : Z2;
            }
            float2 L0=Z2, L1=Z2, L2=Z2, L3=Z2, L4=Z2, L5=Z2;
            #pragma unroll
            for (int j = 0; j < R; ++j) {
                const int sa = (i + j + (K - R)) % K;
                const int sb = (i + (K - 1 - j) + (K - R)) % K;
                float2 a0 = r0[sa], b0 = r0[sb];
                float2 a1 = r1[sa], b1 = r1[sb];
                float2 a2 = r2[sa], b2 = r2[sb];
                float s0x = a0.x + b0.x, s0y = a0.y + b0.y;
                float d0x = a0.x - b0.x, d0y = a0.y - b0.y;
                float s1x = a1.x + b1.x, s1y = a1.y + b1.y;
                float d1x = a1.x - b1.x, d1y = a1.y - b1.y;
                float s2x = a2.x + b2.x, s2y = a2.y + b2.y;
                L0.x = fmaf(fe[j].x, s0x, L0.x); L0.y = fmaf(fe[j].x, s0y, L0.y);
                L3.x = fmaf(fe[j].y, s0x, L3.x); L3.y = fmaf(fe[j].y, s0y, L3.y);
                L2.x = fmaf(fe[j].z, s1x, L2.x); L2.y = fmaf(fe[j].z, s1y, L2.y);
                L5.x = fmaf(fe[j].w, s2x, L5.x); L5.y = fmaf(fe[j].w, s2y, L5.y);
                L1.x = fmaf(fo[j].x, d0x, L1.x); L1.y = fmaf(fo[j].x, d0y, L1.y);
                L4.x = fmaf(fo[j].y, d1x, L4.x); L4.y = fmaf(fo[j].y, d1y, L4.y);
            }
            {   // center tap: slot == i  (odd maps have exact zero center)
                L0.x = fmaf(fe[R].x, r0[i].x, L0.x); L0.y = fmaf(fe[R].x, r0[i].y, L0.y);
                L3.x = fmaf(fe[R].y, r0[i].x, L3.x); L3.y = fmaf(fe[R].y, r0[i].y, L3.y);
                L2.x = fmaf(fe[R].z, r1[i].x, L2.x); L2.y = fmaf(fe[R].z, r1[i].y, L2.y);
                L5.x = fmaf(fe[R].w, r2[i].x, L5.x); L5.y = fmaf(fe[R].w, r2[i].y, L5.y);
            }
            // per-lane products (2 channels folded)
            float p0 = fmaf(L0.y, L0.y, L0.x*L0.x);
            float p1 = fmaf(L1.y, L1.y, L1.x*L1.x);
            float p2 = fmaf(L1.y, L2.y, L1.x*L2.x);
            float p3 = fmaf(L2.y, L2.y, L2.x*L2.x);
            float p4 = fmaf(L3.y, L3.y, L3.x*L3.x);
            float p5 = fmaf(L3.y, L4.y, L3.x*L4.x);
            float p6 = fmaf(L3.y, L5.y, L3.x*L5.x);
            float p7 = fmaf(L4.y, L4.y, L4.x*L4.x);
            float p8 = fmaf(L4.y, L5.y, L4.x*L5.x);
            float p9 = fmaf(L5.y, L5.y, L5.x*L5.x);

            // --- split-butterfly: 10 entries, halving entry set each level ---
            float v0, v1, v2, v3, v4;
            {
                float q, t;
                q = h4 ? p0 : p5; t = __shfl_xor_sync(0xffffffffu, q, 16); v0 = (h4 ? p5 : p0) + t;
                q = h4 ? p1 : p6; t = __shfl_xor_sync(0xffffffffu, q, 16); v1 = (h4 ? p6 : p1) + t;
                q = h4 ? p2 : p7; t = __shfl_xor_sync(0xffffffffu, q, 16); v2 = (h4 ? p7 : p2) + t;
                q = h4 ? p3 : p8; t = __shfl_xor_sync(0xffffffffu, q, 16); v3 = (h4 ? p8 : p3) + t;
                q = h4 ? p4 : p9; t = __shfl_xor_sync(0xffffffffu, q, 16); v4 = (h4 ? p9 : p4) + t;
            }
            float w0, w1, w2;
            {
                float q0 = h3 ? v0 : v3;
                float q1 = h3 ? v1 : v4;
                float q2 = v2;
                float t0s = __shfl_xor_sync(0xffffffffu, q0, 8);
                float t1s = __shfl_xor_sync(0xffffffffu, q1, 8);
                float t2s = __shfl_xor_sync(0xffffffffu, q2, 8);
                if (!h3) { w0 = v0 + t0s; w1 = v1 + t1s; w2 = v2 + t2s; }
                else     { w0 = v3 + t0s; w1 = v4 + t1s; w2 = 0.f; }
            }
            float u0, u1;
            {
                float q0 = h2 ? w0 : (h3 ? w1 : w2);
                float q1 = w1;
                float t0s = __shfl_xor_sync(0xffffffffu, q0, 4);
                float t1s = __shfl_xor_sync(0xffffffffu, q1, 4);
                if (!h3) {
                    if (!h2) { u0 = w0 + t0s; u1 = w1 + t1s; }
                    else     { u0 = w2 + t0s; u1 = 0.f; }
                } else {
                    u0 = (h2 ? w1 : w0) + t0s; u1 = 0.f;
                }
            }
            float z;
            {
                float q = two ? (h1 ? u0 : u1) : u0;
                float t = __shfl_xor_sync(0xffffffffu, q, 2);
                z = (two ? (h1 ? u1 : u0) : u0) + t;
            }
            z += __shfl_xor_sync(0xffffffffu, z, 1);

            if (writer && y < HH)
                PbE[y*WW] = z;
        }
    }
}

// ------- stage 3: separable 7x7 VALID integration + Newton-identity ESPs ----
// Integrator is rank-1 (wy ⊗ wx): two-pass conv in smem, 10 maps per chunk.
__global__ void __launch_bounds__(256) stage3(float* __restrict__ out) {
    __shared__ float sP[10*22*22];
    __shared__ float sQ[10*22*16];
    const int tid = threadIdx.x;
    const int b = blockIdx.z;
    const int y0 = blockIdx.y*16, x0 = blockIdx.x*16;
    const int ty = tid >> 4, tx = tid & 15;
    const int yo = y0 + ty, xo = x0 + tx;
    const bool inb = (yo < HO) && (xo < HO);

    float wy[7], wx[7];
    #pragma unroll
    for (int i = 0; i < 7; ++i) { wy[i] = g_wy[i]; wx[i] = g_wx[i]; }

    float M[20];
    #pragma unroll
    for (int chunk = 0; chunk < 2; ++chunk) {
        for (int idx = tid; idx < 10*484; idx += 256) {
            int se  = idx / 484;
            int rem = idx - se*484;
            int r   = rem / 22;
            int cc2 = rem - r*22;
            int y = y0 + r, x = x0 + cc2;
            float v = 0.f;
            if (y < HH && x < WW)
                v = g_P[(size_t)(chunk*10 + se)*BHW + (size_t)(b*HH + y)*WW + x];
            sP[idx] = v;
        }
        __syncthreads();
        for (int idx = tid; idx < 10*352; idx += 256) {
            int se  = idx / 352;
            int rem = idx - se*352;
            int r   = rem >> 4;
            int cx  = rem & 15;
            const float* row = &sP[se*484 + r*22 + cx];
            float a = 0.f;
            #pragma unroll
            for (int j = 0; j < 7; ++j) a = fmaf(wx[j], row[j], a);
            sQ[idx] = a;
        }
        __syncthreads();
        #pragma unroll
        for (int s = 0; s < 10; ++s) {
            float a = 0.f;
            const float* col = &sQ[s*352 + ty*16 + tx];
            #pragma unroll
            for (int i = 0; i < 7; ++i) a = fmaf(wy[i], col[i*16], a);
            M[chunk*10 + s] = a;
        }
        __syncthreads();
    }
    if (!inb) return;

    const float EPSF = 2.2204460492503131e-16f;
    float res[12];
    #pragma unroll
    for (int s = 0; s < 2; ++s) {
        const float* Ms = M + s*10;
        res[s*6 + 0] = fabsf(Ms[0]) + EPSF;
        {
            float a = Ms[1], bq = Ms[2], c2v = Ms[3];
            float p1 = a + c2v;
            float p2 = a*a + 2.f*bq*bq + c2v*c2v;
            float e1 = p1;
            float e2 = 0.5f*(p1*e1 - p2);
            res[s*6 + 1] = 10.f*(fabsf(e1) + EPSF);
            res[s*6 + 2] = 10.f*sqrtf(fabsf(e2) + EPSF);
        }
        {
            float a = Ms[4], bq = Ms[5], cq = Ms[6], d = Ms[7], e = Ms[8], f = Ms[9];
            float p1 = a + d + f;
            float p2 = a*a + d*d + f*f + 2.f*(bq*bq + cq*cq + e*e);
            float p3 = a*a*a + d*d*d + f*f*f
                     + 3.f*(a*(bq*bq + cq*cq) + d*(bq*bq + e*e) + f*(cq*cq + e*e))
                     + 6.f*bq*cq*e;
            float e1 = p1;
            float e2 = 0.5f*(p1*e1 - p2);
            float e3 = (p1*e2 - p2*e1 + p3)*(1.f/3.f);
            res[s*6 + 3] = 100.f*(fabsf(e1) + EPSF);
            res[s*6 + 4] = 100.f*sqrtf(fabsf(e2) + EPSF);
            res[s*6 + 5] = 100.f*cbrtf(fabsf(e3) + EPSF);
        }
    }
    float* op = out + ((size_t)(b*HO + yo)*HO + xo)*12;
    #pragma unroll
    for (int chn = 0; chn < 12; ++chn) op[chn] = res[chn];
}

// ---------------- launcher ---------------------------------------------------
extern "C" void kernel_launch(void* const* d_in, const int* in_sizes, int n_in,
                              void* d_out, int out_size) {
    const float* in  = (const float*)d_in[0];
    const float* k0  = (const float*)d_in[1];
    const float* k1  = (const float*)d_in[2];
    const float* dgi = (const float*)d_in[3];
    float* out = (float*)d_out;

    factorize<<<1, 256>>>(k0, k1, dgi);

    // both sigmas' x-convs in one pass
    stage1_both<<<dim3(3, HH, BB), 256>>>(in);
    // sigma 0 (R=3): 7 strips of 28 = 4*7
    stage2<3, 28, 4><<<dim3(24, 7, BB), 256>>>(0);
    // sigma 1 (R=6): 5 strips of 39 = 3*13
    stage2<6, 39, 3><<<dim3(24, 5, BB), 256>>>(1);

    stage3<<<dim3(12, 12, BB), 256>>>(out);
}